// round 15
// baseline (speedup 1.0000x reference)
#include <cuda_runtime.h>

// ---------------------------------------------------------------------------
// DNN_SKalmanNet_GSS — R1 structure (proven 94.2us, reproducible to <1us)
// plus two confound-cleared deltas:
//   (a) build_inputs fused into K1's smem staging   (one launch removed)
//   (b) K6 output GEMV split-K x4 + atomicAdd       (13.9 -> 10.3us proven)
// 5 launches: K1 l1/l3 -> K2 gi/gh (4 segs) -> gate(+bias prewrite) ->
//             K5 W1 -> K6 W2 split-K -> d_out.
// Gate kernel stays SEPARATE (fusing it measured +8us in every bundle).
// ---------------------------------------------------------------------------

#define H1   5120
#define H2   4096
#define HID  2048
#define IN1  1120
#define OUT1 1024

__device__ float g_l1[H1];
__device__ float g_l3[H1];
__device__ float g_gi1[3 * HID];
__device__ float g_gh1[3 * HID];
__device__ float g_gi2[3 * HID];
__device__ float g_gh2[3 * HID];
__device__ float g_h1[HID];
__device__ float g_h2[HID];
__device__ float g_hid1[H2];
__device__ float g_hid2[H2];

struct Seg {
    const float* W;
    const float* x;
    const float* b;
    float*       y;
    int          rows;
    int          cols;
    int          act;
};
struct Segs { Seg s[4]; };

// R1-proven multi-segment warp-per-row GEMV (x staged in dynamic smem).
__global__ void gemv_multi_k(Segs segs) {
    Seg s = segs.s[blockIdx.y];
    extern __shared__ float4 sx[];
    const int c4 = s.cols >> 2;

    const float4* __restrict__ xv = (const float4*)s.x;
    for (int j = threadIdx.x; j < c4; j += blockDim.x) sx[j] = xv[j];
    __syncthreads();

    const int lane = threadIdx.x & 31;
    const int warp = (blockIdx.x * blockDim.x + threadIdx.x) >> 5;
    const int nw   = (gridDim.x * blockDim.x) >> 5;

    for (int row = warp; row < s.rows; row += nw) {
        const float4* __restrict__ Wr = (const float4*)s.W + (size_t)row * c4;
        float acc = 0.f;
        #pragma unroll 4
        for (int j = lane; j < c4; j += 32) {
            float4 w  = Wr[j];
            float4 xx = sx[j];
            acc = fmaf(w.x, xx.x, acc);
            acc = fmaf(w.y, xx.y, acc);
            acc = fmaf(w.z, xx.z, acc);
            acc = fmaf(w.w, xx.w, acc);
        }
        #pragma unroll
        for (int o = 16; o; o >>= 1) acc += __shfl_xor_sync(0xffffffffu, acc, o);
        if (lane == 0) {
            float v = acc + s.b[row];
            if (s.act) v = fmaxf(v, 0.f);
            s.y[row] = v;
        }
    }
}

// K1: identical GEMV but input vector is BUILT in smem (no build kernel).
__global__ void k1_input_gemv(const float* __restrict__ si,
                              const float* __restrict__ oi,
                              const float* __restrict__ ds,
                              const float* __restrict__ dob,
                              const float* __restrict__ le,
                              const float* __restrict__ J,
                              const float* __restrict__ l1W,
                              const float* __restrict__ l1b,
                              const float* __restrict__ l3W,
                              const float* __restrict__ l3b) {
    extern __shared__ float4 sx[];
    float* s = (float*)sx;
    const int br = blockIdx.y;
    for (int i = threadIdx.x; i < IN1; i += blockDim.x) {
        float v;
        if (i < 32)       v = br ? oi[i]       : si[i];
        else if (i < 64)  v = br ? dob[i - 32] : ds[i - 32];
        else if (i < 96)  v = le[i - 64];
        else              v = J[i - 96];
        s[i] = v;
    }
    __syncthreads();

    const int lane = threadIdx.x & 31;
    const int warp = (blockIdx.x * blockDim.x + threadIdx.x) >> 5;
    const int nw   = (gridDim.x * blockDim.x) >> 5;
    const float* __restrict__ W = br ? l3W : l1W;
    const float* __restrict__ b = br ? l3b : l1b;
    float* __restrict__ y = br ? g_l3 : g_l1;
    const int c4 = IN1 / 4;

    for (int row = warp; row < H1; row += nw) {
        const float4* __restrict__ Wr = (const float4*)W + (size_t)row * c4;
        float acc = 0.f;
        #pragma unroll 4
        for (int j = lane; j < c4; j += 32) {
            float4 w  = Wr[j];
            float4 xx = sx[j];
            acc = fmaf(w.x, xx.x, acc);
            acc = fmaf(w.y, xx.y, acc);
            acc = fmaf(w.z, xx.z, acc);
            acc = fmaf(w.w, xx.w, acc);
        }
        #pragma unroll
        for (int o = 16; o; o >>= 1) acc += __shfl_xor_sync(0xffffffffu, acc, o);
        if (lane == 0) y[row] = fmaxf(acc + b[row], 0.f);
    }
}

__device__ __forceinline__ float sigmoidf_(float x) {
    return 1.f / (1.f + __expf(-x));
}

// Gate combine; blocks with blockIdx.x == 8 pre-write the output bias into
// d_out so K6's split-K atomics can accumulate on top.
__global__ void gru_gate_k(const float* __restrict__ hn1,
                           const float* __restrict__ hn2,
                           const float* __restrict__ l2b2,
                           const float* __restrict__ l4b2,
                           float* __restrict__ out) {
    const int br = blockIdx.y;
    if (blockIdx.x == 8) {
        const float* b2 = br ? l4b2 : l2b2;
        for (int i = threadIdx.x; i < OUT1; i += blockDim.x)
            out[br * OUT1 + i] = b2[i];
        return;
    }
    int i = blockIdx.x * blockDim.x + threadIdx.x;
    if (i >= HID) return;
    const float* gi = br ? g_gi2 : g_gi1;
    const float* gh = br ? g_gh2 : g_gh1;
    const float* hp = br ? hn2 : hn1;
    float*       h  = br ? g_h2 : g_h1;
    float r = sigmoidf_(gi[i]           + gh[i]);
    float z = sigmoidf_(gi[i + HID]     + gh[i + HID]);
    float n = tanhf(gi[i + 2 * HID] + r * gh[i + 2 * HID]);
    h[i] = (1.f - z) * n + z * hp[i];
}

// K6: split-K x4 output GEMV. y in [0,8): br = y>>2, chunk q = y&3.
// 8 warps/block, 8 rows/block over a 1024-col chunk; atomicAdd partials.
#define CHUNK4 (H2 / 4 / 4)   // 256 float4

__global__ void k6_out_gemv(const float* __restrict__ l2W2,
                            const float* __restrict__ l4W2,
                            float* __restrict__ out) {
    extern __shared__ float4 sx[];
    const int br = blockIdx.y >> 2;
    const int q  = blockIdx.y & 3;
    const float* __restrict__ W = br ? l4W2 : l2W2;
    const float* __restrict__ x = br ? g_hid2 : g_hid1;

    const float4* __restrict__ xv = (const float4*)x + q * CHUNK4;
    for (int j = threadIdx.x; j < CHUNK4; j += blockDim.x) sx[j] = xv[j];
    __syncthreads();

    const int lane = threadIdx.x & 31;
    const int row  = blockIdx.x * 8 + (threadIdx.x >> 5);
    const float4* __restrict__ Wr =
        (const float4*)W + (size_t)row * (H2 / 4) + q * CHUNK4;
    float acc = 0.f;
    #pragma unroll 4
    for (int j = lane; j < CHUNK4; j += 32) {
        float4 w  = Wr[j];
        float4 xx = sx[j];
        acc = fmaf(w.x, xx.x, acc);
        acc = fmaf(w.y, xx.y, acc);
        acc = fmaf(w.z, xx.z, acc);
        acc = fmaf(w.w, xx.w, acc);
    }
    #pragma unroll
    for (int o = 16; o; o >>= 1) acc += __shfl_xor_sync(0xffffffffu, acc, o);
    if (lane == 0) atomicAdd(&out[br * OUT1 + row], acc);
}

static inline Seg mkseg(const float* W, const float* x, const float* b, float* y,
                        int rows, int cols, int act) {
    Seg s; s.W = W; s.x = x; s.b = b; s.y = y; s.rows = rows; s.cols = cols; s.act = act;
    return s;
}

extern "C" void kernel_launch(void* const* d_in, const int* in_sizes, int n_in,
                              void* d_out, int out_size) {
    const float* si    = (const float*)d_in[0];
    const float* oi    = (const float*)d_in[1];
    const float* ds    = (const float*)d_in[2];
    const float* dob   = (const float*)d_in[3];
    const float* le    = (const float*)d_in[4];
    const float* J     = (const float*)d_in[5];
    const float* l1_W  = (const float*)d_in[6];
    const float* l1_b  = (const float*)d_in[7];
    const float* g1Wih = (const float*)d_in[8];
    const float* g1Whh = (const float*)d_in[9];
    const float* g1bih = (const float*)d_in[10];
    const float* g1bhh = (const float*)d_in[11];
    const float* l2_W1 = (const float*)d_in[12];
    const float* l2_b1 = (const float*)d_in[13];
    const float* l2_W2 = (const float*)d_in[14];
    const float* l2_b2 = (const float*)d_in[15];
    const float* l3_W  = (const float*)d_in[16];
    const float* l3_b  = (const float*)d_in[17];
    const float* g2Wih = (const float*)d_in[18];
    const float* g2Whh = (const float*)d_in[19];
    const float* g2bih = (const float*)d_in[20];
    const float* g2bhh = (const float*)d_in[21];
    const float* l4_W1 = (const float*)d_in[22];
    const float* l4_b1 = (const float*)d_in[23];
    const float* l4_W2 = (const float*)d_in[24];
    const float* l4_b2 = (const float*)d_in[25];
    const float* hn1   = (const float*)d_in[26];
    const float* hn2   = (const float*)d_in[27];
    float* out = (float*)d_out;

    float *p_l1, *p_l3, *p_gi1, *p_gh1, *p_gi2, *p_gh2, *p_h1, *p_h2;
    float *p_hid1, *p_hid2;
    cudaGetSymbolAddress((void**)&p_l1,   g_l1);
    cudaGetSymbolAddress((void**)&p_l3,   g_l3);
    cudaGetSymbolAddress((void**)&p_gi1,  g_gi1);
    cudaGetSymbolAddress((void**)&p_gh1,  g_gh1);
    cudaGetSymbolAddress((void**)&p_gi2,  g_gi2);
    cudaGetSymbolAddress((void**)&p_gh2,  g_gh2);
    cudaGetSymbolAddress((void**)&p_h1,   g_h1);
    cudaGetSymbolAddress((void**)&p_h2,   g_h2);
    cudaGetSymbolAddress((void**)&p_hid1, g_hid1);
    cudaGetSymbolAddress((void**)&p_hid2, g_hid2);

    const Seg z = mkseg(nullptr, nullptr, nullptr, nullptr, 0, 0, 0);

    // K1: l1/l3 with input built in smem (640 blocks x 2)
    k1_input_gemv<<<dim3(H1 / 8, 2), 256, IN1 * sizeof(float)>>>(
        si, oi, ds, dob, le, J, l1_W, l1_b, l3_W, l3_b);

    // K2: GRU pre-gates, 4 segments (768 blocks x 4) — unchanged from R1
    {
        Segs sg;
        sg.s[0] = mkseg(g1Wih, p_l1, g1bih, p_gi1, 3 * HID, H1,  0);
        sg.s[1] = mkseg(g1Whh, hn1,  g1bhh, p_gh1, 3 * HID, HID, 0);
        sg.s[2] = mkseg(g2Wih, p_l3, g2bih, p_gi2, 3 * HID, H1,  0);
        sg.s[3] = mkseg(g2Whh, hn2,  g2bhh, p_gh2, 3 * HID, HID, 0);
        gemv_multi_k<<<dim3((3 * HID) / 8, 4), 256, H1 * sizeof(float)>>>(sg);
    }

    // Gate (+ bias prewrite in the extra block column)
    gru_gate_k<<<dim3(HID / 256 + 1, 2), 256>>>(hn1, hn2, l2_b2, l4_b2, out);

    // K5: hidden = relu(W1 @ h + b1) (512 blocks x 2) — unchanged from R1
    {
        Segs sg;
        sg.s[0] = mkseg(l2_W1, p_h1, l2_b1, p_hid1, H2, HID, 1);
        sg.s[1] = mkseg(l4_W1, p_h2, l4_b1, p_hid2, H2, HID, 1);
        sg.s[2] = z; sg.s[3] = z;
        gemv_multi_k<<<dim3(H2 / 8, 2), 256, HID * sizeof(float)>>>(sg);
    }

    // K6: split-K x4 (128 blocks x 8), atomicAdd onto pre-written bias
    k6_out_gemv<<<dim3(OUT1 / 8, 8), 256, CHUNK4 * sizeof(float4)>>>(
        l2_W2, l4_W2, out);

    (void)in_sizes; (void)n_in; (void)out_size;
}

// round 16
// speedup vs baseline: 1.0414x; 1.0414x over previous
#include <cuda_runtime.h>

// ---------------------------------------------------------------------------
// DNN_SKalmanNet_GSS — dual-branch STREAM-PARALLEL pipeline (graph fork/join).
// The Pk and Sk branches are fully independent; gh=Whh@hn depends only on
// inputs. Topology (events; all kernels R1-proven warp-per-row GEMV):
//   s0: l1(23MB) -> gi1(126MB) -> [eGh1] gate1 -> W1a(33.5MB) -> W2a(17MB)
//   sB: l3       -> gi2        -> [eGh2] gate2 -> W1b        -> W2b
//   sC: gh1(50MB) -> eGh1          sD: gh2(50MB) -> eGh2
// Critical path/branch = 199.5MB at shared ~6.8TB/s + gate; ramps overlap
// the other branch. Serial-sum was 94.2us; floor is 73us.
// ---------------------------------------------------------------------------

#define H1   5120
#define H2   4096
#define HID  2048
#define IN1  1120
#define OUT1 1024

__device__ float g_l1[H1];
__device__ float g_l3[H1];
__device__ float g_gi1[3 * HID];
__device__ float g_gh1[3 * HID];
__device__ float g_gi2[3 * HID];
__device__ float g_gh2[3 * HID];
__device__ float g_h1[HID];
__device__ float g_h2[HID];
__device__ float g_hid1[H2];
__device__ float g_hid2[H2];

// Generic warp-per-row GEMV, x staged in dynamic smem (R1-proven loop).
__global__ void k_gemv(const float* __restrict__ W,
                       const float* __restrict__ x,
                       const float* __restrict__ b,
                       float* __restrict__ y,
                       int rows, int c4, int act) {
    extern __shared__ float4 sx[];
    const float4* __restrict__ xv = (const float4*)x;
    for (int j = threadIdx.x; j < c4; j += blockDim.x) sx[j] = xv[j];
    __syncthreads();

    const int lane = threadIdx.x & 31;
    const int warp = (blockIdx.x * blockDim.x + threadIdx.x) >> 5;
    const int nw   = (gridDim.x * blockDim.x) >> 5;

    for (int row = warp; row < rows; row += nw) {
        const float4* __restrict__ Wr = (const float4*)W + (size_t)row * c4;
        float acc = 0.f;
        #pragma unroll 4
        for (int j = lane; j < c4; j += 32) {
            float4 w  = Wr[j];
            float4 xx = sx[j];
            acc = fmaf(w.x, xx.x, acc);
            acc = fmaf(w.y, xx.y, acc);
            acc = fmaf(w.z, xx.z, acc);
            acc = fmaf(w.w, xx.w, acc);
        }
        #pragma unroll
        for (int o = 16; o; o >>= 1) acc += __shfl_xor_sync(0xffffffffu, acc, o);
        if (lane == 0) {
            float v = acc + b[row];
            if (act) v = fmaxf(v, 0.f);
            y[row] = v;
        }
    }
}

// Branch input layer: build concat input in smem, then relu GEMV.
__global__ void k_l(const float* __restrict__ a,   // state_inno / obs_inno
                    const float* __restrict__ d,   // diff_state / diff_obs
                    const float* __restrict__ le,
                    const float* __restrict__ J,
                    const float* __restrict__ W,
                    const float* __restrict__ b,
                    float* __restrict__ y) {
    extern __shared__ float4 sx[];
    float* s = (float*)sx;
    for (int i = threadIdx.x; i < IN1; i += blockDim.x) {
        float v;
        if (i < 32)       v = a[i];
        else if (i < 64)  v = d[i - 32];
        else if (i < 96)  v = le[i - 64];
        else              v = J[i - 96];
        s[i] = v;
    }
    __syncthreads();

    const int lane = threadIdx.x & 31;
    const int warp = (blockIdx.x * blockDim.x + threadIdx.x) >> 5;
    const int nw   = (gridDim.x * blockDim.x) >> 5;
    const int c4   = IN1 / 4;
    for (int row = warp; row < H1; row += nw) {
        const float4* __restrict__ Wr = (const float4*)W + (size_t)row * c4;
        float acc = 0.f;
        #pragma unroll 4
        for (int j = lane; j < c4; j += 32) {
            float4 w  = Wr[j];
            float4 xx = sx[j];
            acc = fmaf(w.x, xx.x, acc);
            acc = fmaf(w.y, xx.y, acc);
            acc = fmaf(w.z, xx.z, acc);
            acc = fmaf(w.w, xx.w, acc);
        }
        #pragma unroll
        for (int o = 16; o; o >>= 1) acc += __shfl_xor_sync(0xffffffffu, acc, o);
        if (lane == 0) y[row] = fmaxf(acc + b[row], 0.f);
    }
}

// GRU gate combine for one branch (r,z,n order): h = (1-z)*n + z*hp
__global__ void k_gate(const float* __restrict__ gi,
                       const float* __restrict__ gh,
                       const float* __restrict__ hp,
                       float* __restrict__ h) {
    int i = blockIdx.x * blockDim.x + threadIdx.x;
    if (i >= HID) return;
    float r = 1.f / (1.f + __expf(-(gi[i]       + gh[i])));
    float z = 1.f / (1.f + __expf(-(gi[i + HID] + gh[i + HID])));
    float n = tanhf(gi[i + 2 * HID] + r * gh[i + 2 * HID]);
    h[i] = (1.f - z) * n + z * hp[i];
}

extern "C" void kernel_launch(void* const* d_in, const int* in_sizes, int n_in,
                              void* d_out, int out_size) {
    const float* si    = (const float*)d_in[0];
    const float* oi    = (const float*)d_in[1];
    const float* ds    = (const float*)d_in[2];
    const float* dob   = (const float*)d_in[3];
    const float* le    = (const float*)d_in[4];
    const float* J     = (const float*)d_in[5];
    const float* l1_W  = (const float*)d_in[6];
    const float* l1_b  = (const float*)d_in[7];
    const float* g1Wih = (const float*)d_in[8];
    const float* g1Whh = (const float*)d_in[9];
    const float* g1bih = (const float*)d_in[10];
    const float* g1bhh = (const float*)d_in[11];
    const float* l2_W1 = (const float*)d_in[12];
    const float* l2_b1 = (const float*)d_in[13];
    const float* l2_W2 = (const float*)d_in[14];
    const float* l2_b2 = (const float*)d_in[15];
    const float* l3_W  = (const float*)d_in[16];
    const float* l3_b  = (const float*)d_in[17];
    const float* g2Wih = (const float*)d_in[18];
    const float* g2Whh = (const float*)d_in[19];
    const float* g2bih = (const float*)d_in[20];
    const float* g2bhh = (const float*)d_in[21];
    const float* l4_W1 = (const float*)d_in[22];
    const float* l4_b1 = (const float*)d_in[23];
    const float* l4_W2 = (const float*)d_in[24];
    const float* l4_b2 = (const float*)d_in[25];
    const float* hn1   = (const float*)d_in[26];
    const float* hn2   = (const float*)d_in[27];
    float* out = (float*)d_out;

    float *p_l1, *p_l3, *p_gi1, *p_gh1, *p_gi2, *p_gh2, *p_h1, *p_h2;
    float *p_hid1, *p_hid2;
    cudaGetSymbolAddress((void**)&p_l1,   g_l1);
    cudaGetSymbolAddress((void**)&p_l3,   g_l3);
    cudaGetSymbolAddress((void**)&p_gi1,  g_gi1);
    cudaGetSymbolAddress((void**)&p_gh1,  g_gh1);
    cudaGetSymbolAddress((void**)&p_gi2,  g_gi2);
    cudaGetSymbolAddress((void**)&p_gh2,  g_gh2);
    cudaGetSymbolAddress((void**)&p_h1,   g_h1);
    cudaGetSymbolAddress((void**)&p_h2,   g_h2);
    cudaGetSymbolAddress((void**)&p_hid1, g_hid1);
    cudaGetSymbolAddress((void**)&p_hid2, g_hid2);

    // Streams/events created once on the first (uncaptured) correctness call;
    // reused verbatim during graph capture. No device memory involved.
    static cudaStream_t sB = 0, sC = 0, sD = 0;
    static cudaEvent_t  eFork = 0, eGh1 = 0, eGh2 = 0, eB = 0;
    if (sB == 0) {
        cudaStreamCreateWithFlags(&sB, cudaStreamNonBlocking);
        cudaStreamCreateWithFlags(&sC, cudaStreamNonBlocking);
        cudaStreamCreateWithFlags(&sD, cudaStreamNonBlocking);
        cudaEventCreateWithFlags(&eFork, cudaEventDisableTiming);
        cudaEventCreateWithFlags(&eGh1,  cudaEventDisableTiming);
        cudaEventCreateWithFlags(&eGh2,  cudaEventDisableTiming);
        cudaEventCreateWithFlags(&eB,    cudaEventDisableTiming);
    }

    // ---- fork ----
    cudaEventRecord(eFork, 0);
    cudaStreamWaitEvent(sB, eFork, 0);
    cudaStreamWaitEvent(sC, eFork, 0);
    cudaStreamWaitEvent(sD, eFork, 0);

    // ---- side streams: gh = Whh @ hn (input-only deps) ----
    k_gemv<<<768, 256, HID * sizeof(float), sC>>>(
        g1Whh, hn1, g1bhh, p_gh1, 3 * HID, HID / 4, 0);
    cudaEventRecord(eGh1, sC);
    k_gemv<<<768, 256, HID * sizeof(float), sD>>>(
        g2Whh, hn2, g2bhh, p_gh2, 3 * HID, HID / 4, 0);
    cudaEventRecord(eGh2, sD);

    // ---- branch 1 (stream 0): l1 -> gi1 -> gate1 -> W1a -> W2a ----
    k_l<<<640, 256, IN1 * sizeof(float)>>>(si, ds, le, J, l1_W, l1_b, p_l1);
    k_gemv<<<768, 256, H1 * sizeof(float)>>>(
        g1Wih, p_l1, g1bih, p_gi1, 3 * HID, H1 / 4, 0);
    cudaStreamWaitEvent(0, eGh1, 0);
    k_gate<<<HID / 256, 256>>>(p_gi1, p_gh1, hn1, p_h1);
    k_gemv<<<512, 256, HID * sizeof(float)>>>(
        l2_W1, p_h1, l2_b1, p_hid1, H2, HID / 4, 1);
    k_gemv<<<128, 256, H2 * sizeof(float)>>>(
        l2_W2, p_hid1, l2_b2, out, OUT1, H2 / 4, 0);

    // ---- branch 2 (stream sB): l3 -> gi2 -> gate2 -> W1b -> W2b ----
    k_l<<<640, 256, IN1 * sizeof(float), sB>>>(oi, dob, le, J, l3_W, l3_b, p_l3);
    k_gemv<<<768, 256, H1 * sizeof(float), sB>>>(
        g2Wih, p_l3, g2bih, p_gi2, 3 * HID, H1 / 4, 0);
    cudaStreamWaitEvent(sB, eGh2, 0);
    k_gate<<<HID / 256, 256, 0, sB>>>(p_gi2, p_gh2, hn2, p_h2);
    k_gemv<<<512, 256, HID * sizeof(float), sB>>>(
        l4_W1, p_h2, l4_b1, p_hid2, H2, HID / 4, 1);
    k_gemv<<<128, 256, H2 * sizeof(float), sB>>>(
        l4_W2, p_hid2, l4_b2, out + OUT1, OUT1, H2 / 4, 0);

    // ---- join ----
    cudaEventRecord(eB, sB);
    cudaStreamWaitEvent(0, eB, 0);

    (void)in_sizes; (void)n_in; (void)out_size;
}

// round 17
// speedup vs baseline: 1.0590x; 1.0169x over previous
#include <cuda_runtime.h>

// ---------------------------------------------------------------------------
// DNN_SKalmanNet_GSS — dual-branch stream-parallel pipeline v2.
// R16 (90.5us) + fixes: critical-path-first launch order (l before gh);
// W2 tails split-K x4 with atomicAdd onto gate-prewritten bias.
//   s0: l1 -> gi1 -> [eGh1] gate1(+bias) -> W1a -> W2a splitK -> out[0:1024]
//   sB: l3 -> gi2 -> [eGh2] gate2(+bias) -> W1b -> W2b splitK -> out[1024:]
//   sC: gh1 -> eGh1   sD: gh2 -> eGh2   (launched AFTER l1/l3)
// ---------------------------------------------------------------------------

#define H1   5120
#define H2   4096
#define HID  2048
#define IN1  1120
#define OUT1 1024
#define CHUNK4 (H2 / 4 / 4)   // 256 float4 per split-K chunk

__device__ float g_l1[H1];
__device__ float g_l3[H1];
__device__ float g_gi1[3 * HID];
__device__ float g_gh1[3 * HID];
__device__ float g_gi2[3 * HID];
__device__ float g_gh2[3 * HID];
__device__ float g_h1[HID];
__device__ float g_h2[HID];
__device__ float g_hid1[H2];
__device__ float g_hid2[H2];

// Generic warp-per-row GEMV, x staged in dynamic smem (R1-proven loop).
__global__ void k_gemv(const float* __restrict__ W,
                       const float* __restrict__ x,
                       const float* __restrict__ b,
                       float* __restrict__ y,
                       int rows, int c4, int act) {
    extern __shared__ float4 sx[];
    const float4* __restrict__ xv = (const float4*)x;
    for (int j = threadIdx.x; j < c4; j += blockDim.x) sx[j] = xv[j];
    __syncthreads();

    const int lane = threadIdx.x & 31;
    const int warp = (blockIdx.x * blockDim.x + threadIdx.x) >> 5;
    const int nw   = (gridDim.x * blockDim.x) >> 5;

    for (int row = warp; row < rows; row += nw) {
        const float4* __restrict__ Wr = (const float4*)W + (size_t)row * c4;
        float acc = 0.f;
        #pragma unroll 4
        for (int j = lane; j < c4; j += 32) {
            float4 w  = Wr[j];
            float4 xx = sx[j];
            acc = fmaf(w.x, xx.x, acc);
            acc = fmaf(w.y, xx.y, acc);
            acc = fmaf(w.z, xx.z, acc);
            acc = fmaf(w.w, xx.w, acc);
        }
        #pragma unroll
        for (int o = 16; o; o >>= 1) acc += __shfl_xor_sync(0xffffffffu, acc, o);
        if (lane == 0) {
            float v = acc + b[row];
            if (act) v = fmaxf(v, 0.f);
            y[row] = v;
        }
    }
}

// Branch input layer: build concat input in smem, then relu GEMV.
__global__ void k_l(const float* __restrict__ a,
                    const float* __restrict__ d,
                    const float* __restrict__ le,
                    const float* __restrict__ J,
                    const float* __restrict__ W,
                    const float* __restrict__ b,
                    float* __restrict__ y) {
    extern __shared__ float4 sx[];
    float* s = (float*)sx;
    for (int i = threadIdx.x; i < IN1; i += blockDim.x) {
        float v;
        if (i < 32)       v = a[i];
        else if (i < 64)  v = d[i - 32];
        else if (i < 96)  v = le[i - 64];
        else              v = J[i - 96];
        s[i] = v;
    }
    __syncthreads();

    const int lane = threadIdx.x & 31;
    const int warp = (blockIdx.x * blockDim.x + threadIdx.x) >> 5;
    const int nw   = (gridDim.x * blockDim.x) >> 5;
    const int c4   = IN1 / 4;
    for (int row = warp; row < H1; row += nw) {
        const float4* __restrict__ Wr = (const float4*)W + (size_t)row * c4;
        float acc = 0.f;
        #pragma unroll 4
        for (int j = lane; j < c4; j += 32) {
            float4 w  = Wr[j];
            float4 xx = sx[j];
            acc = fmaf(w.x, xx.x, acc);
            acc = fmaf(w.y, xx.y, acc);
            acc = fmaf(w.z, xx.z, acc);
            acc = fmaf(w.w, xx.w, acc);
        }
        #pragma unroll
        for (int o = 16; o; o >>= 1) acc += __shfl_xor_sync(0xffffffffu, acc, o);
        if (lane == 0) y[row] = fmaxf(acc + b[row], 0.f);
    }
}

// GRU gate combine for one branch; block 8 pre-writes the output bias into
// this branch's half of d_out (split-K W2 atomics accumulate on top).
__global__ void k_gate(const float* __restrict__ gi,
                       const float* __restrict__ gh,
                       const float* __restrict__ hp,
                       float* __restrict__ h,
                       const float* __restrict__ b2,
                       float* __restrict__ outHalf) {
    if (blockIdx.x == 8) {
        for (int i = threadIdx.x; i < OUT1; i += blockDim.x)
            outHalf[i] = b2[i];
        return;
    }
    int i = blockIdx.x * blockDim.x + threadIdx.x;
    if (i >= HID) return;
    float r = 1.f / (1.f + __expf(-(gi[i]       + gh[i])));
    float z = 1.f / (1.f + __expf(-(gi[i + HID] + gh[i + HID])));
    float n = tanhf(gi[i + 2 * HID] + r * gh[i + 2 * HID]);
    h[i] = (1.f - z) * n + z * hp[i];
}

// Split-K x4 output GEMV (one branch). blockIdx.y = chunk q.
// 8 warps/block, 8 rows/block, 1024-col partial -> atomicAdd.
__global__ void k_out_splitk(const float* __restrict__ W,
                             const float* __restrict__ x,
                             float* __restrict__ outHalf) {
    extern __shared__ float4 sx[];
    const int q = blockIdx.y;
    const float4* __restrict__ xv = (const float4*)x + q * CHUNK4;
    for (int j = threadIdx.x; j < CHUNK4; j += blockDim.x) sx[j] = xv[j];
    __syncthreads();

    const int lane = threadIdx.x & 31;
    const int row  = blockIdx.x * 8 + (threadIdx.x >> 5);
    const float4* __restrict__ Wr =
        (const float4*)W + (size_t)row * (H2 / 4) + q * CHUNK4;
    float acc = 0.f;
    #pragma unroll 4
    for (int j = lane; j < CHUNK4; j += 32) {
        float4 w  = Wr[j];
        float4 xx = sx[j];
        acc = fmaf(w.x, xx.x, acc);
        acc = fmaf(w.y, xx.y, acc);
        acc = fmaf(w.z, xx.z, acc);
        acc = fmaf(w.w, xx.w, acc);
    }
    #pragma unroll
    for (int o = 16; o; o >>= 1) acc += __shfl_xor_sync(0xffffffffu, acc, o);
    if (lane == 0) atomicAdd(&outHalf[row], acc);
}

extern "C" void kernel_launch(void* const* d_in, const int* in_sizes, int n_in,
                              void* d_out, int out_size) {
    const float* si    = (const float*)d_in[0];
    const float* oi    = (const float*)d_in[1];
    const float* ds    = (const float*)d_in[2];
    const float* dob   = (const float*)d_in[3];
    const float* le    = (const float*)d_in[4];
    const float* J     = (const float*)d_in[5];
    const float* l1_W  = (const float*)d_in[6];
    const float* l1_b  = (const float*)d_in[7];
    const float* g1Wih = (const float*)d_in[8];
    const float* g1Whh = (const float*)d_in[9];
    const float* g1bih = (const float*)d_in[10];
    const float* g1bhh = (const float*)d_in[11];
    const float* l2_W1 = (const float*)d_in[12];
    const float* l2_b1 = (const float*)d_in[13];
    const float* l2_W2 = (const float*)d_in[14];
    const float* l2_b2 = (const float*)d_in[15];
    const float* l3_W  = (const float*)d_in[16];
    const float* l3_b  = (const float*)d_in[17];
    const float* g2Wih = (const float*)d_in[18];
    const float* g2Whh = (const float*)d_in[19];
    const float* g2bih = (const float*)d_in[20];
    const float* g2bhh = (const float*)d_in[21];
    const float* l4_W1 = (const float*)d_in[22];
    const float* l4_b1 = (const float*)d_in[23];
    const float* l4_W2 = (const float*)d_in[24];
    const float* l4_b2 = (const float*)d_in[25];
    const float* hn1   = (const float*)d_in[26];
    const float* hn2   = (const float*)d_in[27];
    float* out = (float*)d_out;

    float *p_l1, *p_l3, *p_gi1, *p_gh1, *p_gi2, *p_gh2, *p_h1, *p_h2;
    float *p_hid1, *p_hid2;
    cudaGetSymbolAddress((void**)&p_l1,   g_l1);
    cudaGetSymbolAddress((void**)&p_l3,   g_l3);
    cudaGetSymbolAddress((void**)&p_gi1,  g_gi1);
    cudaGetSymbolAddress((void**)&p_gh1,  g_gh1);
    cudaGetSymbolAddress((void**)&p_gi2,  g_gi2);
    cudaGetSymbolAddress((void**)&p_gh2,  g_gh2);
    cudaGetSymbolAddress((void**)&p_h1,   g_h1);
    cudaGetSymbolAddress((void**)&p_h2,   g_h2);
    cudaGetSymbolAddress((void**)&p_hid1, g_hid1);
    cudaGetSymbolAddress((void**)&p_hid2, g_hid2);

    static cudaStream_t sB = 0, sC = 0, sD = 0;
    static cudaEvent_t  eFork = 0, eGh1 = 0, eGh2 = 0, eB = 0;
    if (sB == 0) {
        cudaStreamCreateWithFlags(&sB, cudaStreamNonBlocking);
        cudaStreamCreateWithFlags(&sC, cudaStreamNonBlocking);
        cudaStreamCreateWithFlags(&sD, cudaStreamNonBlocking);
        cudaEventCreateWithFlags(&eFork, cudaEventDisableTiming);
        cudaEventCreateWithFlags(&eGh1,  cudaEventDisableTiming);
        cudaEventCreateWithFlags(&eGh2,  cudaEventDisableTiming);
        cudaEventCreateWithFlags(&eB,    cudaEventDisableTiming);
    }

    // ---- fork ----
    cudaEventRecord(eFork, 0);
    cudaStreamWaitEvent(sB, eFork, 0);
    cudaStreamWaitEvent(sC, eFork, 0);
    cudaStreamWaitEvent(sD, eFork, 0);

    // ---- critical path FIRST: l1 (s0) and l3 (sB) ----
    k_l<<<640, 256, IN1 * sizeof(float)>>>(si, ds, le, J, l1_W, l1_b, p_l1);
    k_l<<<640, 256, IN1 * sizeof(float), sB>>>(oi, dob, le, J, l3_W, l3_b, p_l3);

    // ---- then deferrable gh work (fills remaining bandwidth) ----
    k_gemv<<<768, 256, HID * sizeof(float), sC>>>(
        g1Whh, hn1, g1bhh, p_gh1, 3 * HID, HID / 4, 0);
    cudaEventRecord(eGh1, sC);
    k_gemv<<<768, 256, HID * sizeof(float), sD>>>(
        g2Whh, hn2, g2bhh, p_gh2, 3 * HID, HID / 4, 0);
    cudaEventRecord(eGh2, sD);

    // ---- branch 1 (s0): gi1 -> gate1(+bias) -> W1a -> W2a splitK ----
    k_gemv<<<768, 256, H1 * sizeof(float)>>>(
        g1Wih, p_l1, g1bih, p_gi1, 3 * HID, H1 / 4, 0);
    cudaStreamWaitEvent(0, eGh1, 0);
    k_gate<<<9, 256>>>(p_gi1, p_gh1, hn1, p_h1, l2_b2, out);
    k_gemv<<<512, 256, HID * sizeof(float)>>>(
        l2_W1, p_h1, l2_b1, p_hid1, H2, HID / 4, 1);
    k_out_splitk<<<dim3(OUT1 / 8, 4), 256, CHUNK4 * sizeof(float4)>>>(
        l2_W2, p_hid1, out);

    // ---- branch 2 (sB): gi2 -> gate2(+bias) -> W1b -> W2b splitK ----
    k_gemv<<<768, 256, H1 * sizeof(float), sB>>>(
        g2Wih, p_l3, g2bih, p_gi2, 3 * HID, H1 / 4, 0);
    cudaStreamWaitEvent(sB, eGh2, 0);
    k_gate<<<9, 256, 0, sB>>>(p_gi2, p_gh2, hn2, p_h2, l4_b2, out + OUT1);
    k_gemv<<<512, 256, HID * sizeof(float), sB>>>(
        l4_W1, p_h2, l4_b1, p_hid2, H2, HID / 4, 1);
    k_out_splitk<<<dim3(OUT1 / 8, 4), 256, CHUNK4 * sizeof(float4), sB>>>(
        l4_W2, p_hid2, out + OUT1);

    // ---- join ----
    cudaEventRecord(eB, sB);
    cudaStreamWaitEvent(0, eB, 0);

    (void)in_sizes; (void)n_in; (void)out_size;
}